// round 17
// baseline (speedup 1.0000x reference)
#include <cuda_runtime.h>
#include <cuda_fp16.h>
#include <math.h>

#define GN 16384
#define ECH 256
#define NB 8
#define HB 4
static const size_t BSTR = (size_t)ECH * GN;
static const size_t TOT4 = (size_t)HB * BSTR;
typedef __half2 h2;

__device__ __half g_emb[33554432];
__device__ __half g_pre[33554432];
__device__ float g_pu[HB * 16 * 256 * 256];
__device__ float g_plw[HB * 8 * 256 * 512];
__device__ __half g_fh[33554432];
__device__ __half g_nh[33554432];
__device__ __half g_qkvh[50331648];
__device__ __half g_th[16777216];
__device__ __half g_kvh[8388608];
__device__ __half g_suh[1048576];
__device__ __half g_slh[1048576];
__device__ __half g_wh[524288];

__device__ __forceinline__ unsigned s2u(const void* p) {
    return (unsigned)__cvta_generic_to_shared(p);
}
__device__ __forceinline__ void cpa16(unsigned dst, const void* src) {
    asm volatile("cp.async.cg.shared.global [%0], [%1], 16;" :: "r"(dst), "l"(src));
}
__device__ __forceinline__ void cp_commit() { asm volatile("cp.async.commit_group;"); }
__device__ __forceinline__ void cp_wait0() { asm volatile("cp.async.wait_group 0;" ::: "memory"); }
__device__ __forceinline__ void cp_wait1() { asm volatile("cp.async.wait_group 1;" ::: "memory"); }

__device__ __forceinline__ void ldm4(unsigned* r, unsigned a) {
    asm volatile("ldmatrix.sync.aligned.m8n8.x4.shared.b16 {%0,%1,%2,%3}, [%4];"
                 : "=r"(r[0]), "=r"(r[1]), "=r"(r[2]), "=r"(r[3]) : "r"(a));
}
__device__ __forceinline__ void ldm4t(unsigned* r, unsigned a) {
    asm volatile("ldmatrix.sync.aligned.m8n8.x4.trans.shared.b16 {%0,%1,%2,%3}, [%4];"
                 : "=r"(r[0]), "=r"(r[1]), "=r"(r[2]), "=r"(r[3]) : "r"(a));
}
__device__ __forceinline__ void mma_f16(float* c, const unsigned* a, unsigned b0, unsigned b1) {
    asm volatile(
        "mma.sync.aligned.m16n8k16.row.col.f32.f16.f16.f32 "
        "{%0,%1,%2,%3},{%4,%5,%6,%7},{%8,%9},{%0,%1,%2,%3};"
        : "+f"(c[0]), "+f"(c[1]), "+f"(c[2]), "+f"(c[3])
        : "r"(a[0]), "r"(a[1]), "r"(a[2]), "r"(a[3]), "r"(b0), "r"(b1));
}
__device__ __forceinline__ h2 hi2(float a, float b) {
    return __floats2half2_rn(a, b);
}
__device__ __forceinline__ float gelu_exact(float x) {
    return 0.5f * x * (1.0f + erff(x * 0.70710678118654752f));
}
__device__ __forceinline__ float brsum(float v, float* sb) {
    int t = threadIdx.x;
    sb[t] = v; __syncthreads();
    for (int s = 128; s > 0; s >>= 1) { if (t < s) sb[t] += sb[t + s]; __syncthreads(); }
    float r = sb[0]; __syncthreads(); return r;
}
__device__ __forceinline__ float brmax(float v, float* sb) {
    int t = threadIdx.x;
    sb[t] = v; __syncthreads();
    for (int s = 128; s > 0; s >>= 1) { if (t < s) sb[t] = fmaxf(sb[t], sb[t + s]); __syncthreads(); }
    float r = sb[0]; __syncthreads(); return r;
}

// conv GEMM smem (128m x 64n CTA tile): A 10240 + B(pitch 72) 4608 per 32-k sub
#define SUBB 14848
#define CBUF2 29696            // 64-k block
#define CSMEM2 59392           // 2 buffers
// NT smem (unchanged 128x128 tile)
#define NSUB 20480
#define NBUF2 40960
#define NSMEM 81920

// conv1x1 GEMM (fp16, CTA 128x64, 3 CTAs/SM): C[b](M x GN) = Ah[b](M x K) @ Bh[b](K x GN)
// epi bits: 1 gelu, 2 +R(half), 8 fp32 out C, 32 half out Ch. Row-group stride oGrp.
__global__ __launch_bounds__(256, 3)
void gemm_cp(const __half* __restrict__ Ah, size_t aBs,
             const __half* __restrict__ Bh, size_t bBs,
             float* __restrict__ C, __half* __restrict__ Ch,
             size_t cBs, size_t oGrp, const __half* __restrict__ R,
             int K, int epi) {
    extern __shared__ char smem[];
    int tid = threadIdx.x, wid = tid >> 5, lane = tid & 31;
    int wm = wid & 3, wn = wid >> 2;       // 4(m) x 2(n) warps
    int oBase = blockIdx.y * 128, nBase = blockIdx.x * 64;
    int b = blockIdx.z;
    Ah += (size_t)b * aBs;
    Bh += (size_t)b * bBs;

    unsigned sb0 = s2u(smem);
    auto stage = [&](int kk, int buf) {
        unsigned base = sb0 + buf * CBUF2;
#pragma unroll
        for (int sub = 0; sub < 2; sub++) {
            int k0 = kk + sub * 32;
            unsigned sbase = base + sub * SUBB;
#pragma unroll
            for (int i = 0; i < 2; i++) {       // A: 512 cpa16
                int c = tid + 256 * i;
                int r = c >> 2, s = c & 3;
                const __half* src = Ah + (size_t)(oBase + r) * K + k0 + s * 8;
                cpa16(sbase + r * 80 + s * 16, src);
            }
            {                                    // B: 256 cpa16 (32 rows x 64 halfs)
                int r = tid >> 3, s = tid & 7;
                const __half* src = Bh + (size_t)(k0 + r) * GN + nBase + s * 8;
                cpa16(sbase + 10240 + r * 144 + s * 16, src);
            }
        }
        cp_commit();
    };

    float acc[2][4][4];
#pragma unroll
    for (int i = 0; i < 2; i++)
#pragma unroll
        for (int j = 0; j < 4; j++)
#pragma unroll
            for (int q = 0; q < 4; q++) acc[i][j][q] = 0.0f;

    unsigned aRow = (unsigned)(wm * 32 + (lane & 15));
    unsigned aKof = (unsigned)((lane >> 4) * 8);
    unsigned bKrow = (unsigned)((lane & 7) + ((lane >> 3) & 1) * 8);
    unsigned bNcol = (unsigned)(wn * 32 + ((lane >> 4) & 1) * 8);

    int KT = K >> 6;
    stage(0, 0);
    for (int t = 0; t < KT; t++) {
        int cb = t & 1;
        if (t + 1 < KT) {
            stage((t + 1) * 64, cb ^ 1);
            cp_wait1();
        } else {
            cp_wait0();
        }
        __syncthreads();

#pragma unroll
        for (int sub = 0; sub < 2; sub++) {
            const __half* sA0 = (const __half*)(smem + cb * CBUF2 + sub * SUBB);
            const __half* sB0 = (const __half*)(smem + cb * CBUF2 + sub * SUBB + 10240);
#pragma unroll
            for (int ks = 0; ks < 32; ks += 16) {
                unsigned ah[2][4], bh2r[2][4];
#pragma unroll
                for (int mt = 0; mt < 2; mt++)
                    ldm4(ah[mt], s2u(&sA0[(aRow + mt * 16) * 40 + ks + aKof]));
#pragma unroll
                for (int n2 = 0; n2 < 2; n2++)
                    ldm4t(bh2r[n2], s2u(&sB0[(bKrow + ks) * 72 + bNcol + n2 * 16]));
#pragma unroll
                for (int mt = 0; mt < 2; mt++)
#pragma unroll
                    for (int nt = 0; nt < 4; nt++)
                        mma_f16(acc[mt][nt], ah[mt], bh2r[nt >> 1][(nt & 1) * 2],
                                bh2r[nt >> 1][(nt & 1) * 2 + 1]);
            }
        }
        __syncthreads();
    }

    int g = lane >> 2, tg = lane & 3;
#pragma unroll
    for (int mt = 0; mt < 2; mt++) {
#pragma unroll
        for (int nt = 0; nt < 4; nt++) {
            int r0 = oBase + wm * 32 + mt * 16 + g;
            int col = nBase + wn * 32 + nt * 8 + tg * 2;
            float* c = acc[mt][nt];
#pragma unroll
            for (int h2i = 0; h2i < 2; h2i++) {
                int rr = r0 + h2i * 8;
                size_t base = (size_t)(rr >> 8) * oGrp + (size_t)b * cBs
                            + (size_t)(rr & 255) * GN + col;
                float o0 = c[2 * h2i], o1 = c[2 * h2i + 1];
                if (epi & 2) {
                    float2 rv = __half22float2(*(const h2*)&R[base]);
                    o0 += rv.x; o1 += rv.y;
                }
                if (epi & 1) { o0 = gelu_exact(o0); o1 = gelu_exact(o1); }
                if (epi & 8) *(float2*)&C[base] = make_float2(o0, o1);
                if (epi & 32) *(h2*)&Ch[base] = hi2(o0, o1);
            }
        }
    }
}

// NT score GEMM (fp16, unchanged 128x128 tile): P[z][i][j] = sum Qh[i][n] Kh[j][n]
__global__ __launch_bounds__(256, 2)
void gemmnt_cp(const __half* __restrict__ Qh, size_t qBs,
               const __half* __restrict__ Kh, size_t kBs,
               float* __restrict__ P, int J, int nsplit) {
    extern __shared__ char smem[];
    int tid = threadIdx.x, wid = tid >> 5, lane = tid & 31;
    int wm = wid & 1, wn = wid >> 1;
    int z = blockIdx.z, b = z / nsplit, s = z % nsplit;
    Qh += (size_t)b * qBs;
    Kh += (size_t)b * kBs;
    int iBase = blockIdx.y * 128, jBase = blockIdx.x * 128;
    const int chunk = GN / nsplit;
    int n0 = s * chunk;
    unsigned sb0 = s2u(smem);

    auto stage = [&](int kk, int buf) {
        unsigned base = sb0 + buf * NBUF2;
#pragma unroll
        for (int sub = 0; sub < 2; sub++) {
            int k0 = kk + sub * 32;
            unsigned sbase = base + sub * NSUB;
#pragma unroll
            for (int i = 0; i < 4; i++) {
                int c = tid + 256 * i;
                int p = c >> 9, c2 = c & 511;
                int r = c2 >> 2, sg = c2 & 3;
                const __half* src = (p ? Kh + (size_t)(jBase + r) * GN
                                       : Qh + (size_t)(iBase + r) * GN) + n0 + k0 + sg * 8;
                cpa16(sbase + p * 10240 + r * 80 + sg * 16, src);
            }
        }
        cp_commit();
    };

    float acc[4][4][4];
#pragma unroll
    for (int i = 0; i < 4; i++)
#pragma unroll
        for (int j = 0; j < 4; j++)
#pragma unroll
            for (int q = 0; q < 4; q++) acc[i][j][q] = 0.0f;

    unsigned aRow = (unsigned)(wm * 64 + (lane & 15));
    unsigned aKof = (unsigned)((lane >> 4) * 8);
    unsigned bJrow = (unsigned)(wn * 32 + (lane & 7) + ((lane >> 4) & 1) * 8);
    unsigned bKof = (unsigned)(((lane >> 3) & 1) * 8);

    int KT = chunk >> 6;
    stage(0, 0);
    for (int t = 0; t < KT; t++) {
        int cb = t & 1;
        if (t + 1 < KT) {
            stage((t + 1) * 64, cb ^ 1);
            cp_wait1();
        } else {
            cp_wait0();
        }
        __syncthreads();

#pragma unroll
        for (int sub = 0; sub < 2; sub++) {
            const __half* sQ0 = (const __half*)(smem + cb * NBUF2 + sub * NSUB);
            const __half* sK0 = (const __half*)(smem + cb * NBUF2 + sub * NSUB + 10240);
#pragma unroll
            for (int ks = 0; ks < 32; ks += 16) {
                unsigned ah[4][4], bh2r[2][4];
#pragma unroll
                for (int mt = 0; mt < 4; mt++)
                    ldm4(ah[mt], s2u(&sQ0[(aRow + mt * 16) * 40 + ks + aKof]));
#pragma unroll
                for (int n2 = 0; n2 < 2; n2++)
                    ldm4(bh2r[n2], s2u(&sK0[(bJrow + n2 * 16) * 40 + ks + bKof]));
#pragma unroll
                for (int mt = 0; mt < 4; mt++)
#pragma unroll
                    for (int nt = 0; nt < 4; nt++)
                        mma_f16(acc[mt][nt], ah[mt], bh2r[nt >> 1][(nt & 1) * 2],
                                bh2r[nt >> 1][(nt & 1) * 2 + 1]);
            }
        }
        __syncthreads();
    }

    int g = lane >> 2, tg = lane & 3;
#pragma unroll
    for (int mt = 0; mt < 4; mt++) {
#pragma unroll
        for (int nt = 0; nt < 4; nt++) {
            int r0 = iBase + wm * 64 + mt * 16 + g;
            int col = jBase + wn * 32 + nt * 8 + tg * 2;
            float* c = acc[mt][nt];
#pragma unroll
            for (int h2i = 0; h2i < 2; h2i++) {
                size_t base = ((size_t)z * 256 + r0 + h2i * 8) * J + col;
                *(float2*)&P[base] = make_float2(c[2 * h2i], c[2 * h2i + 1]);
            }
        }
    }
}

__global__ __launch_bounds__(256)
void split_w8(const float* w0, const float* w1, const float* w2, const float* w3,
              const float* w4, const float* w5, const float* w6, const float* w7,
              __half* __restrict__ H) {
    const float* srcs[8] = { w0, w1, w2, w3, w4, w5, w6, w7 };
    int w = blockIdx.y;
    const float* X = srcs[w];
    int i = blockIdx.x * 256 + threadIdx.x;
    float4 v = ((const float4*)X)[i];
    size_t o = (size_t)w * 32768 + 2 * i;
    ((h2*)H)[o] = hi2(v.x, v.y);
    ((h2*)H)[o + 1] = hi2(v.z, v.w);
}

__global__ __launch_bounds__(256)
void split_hi(const float* __restrict__ X, __half* __restrict__ H, int n4) {
    int i = blockIdx.x * 256 + threadIdx.x;
    if (i < n4) {
        float4 v = ((const float4*)X)[i];
        ((h2*)H)[2 * i] = hi2(v.x, v.y);
        ((h2*)H)[2 * i + 1] = hi2(v.z, v.w);
    }
}

__global__ __launch_bounds__(256)
void inorm_hh(const __half* __restrict__ X, __half* __restrict__ H,
              const float* __restrict__ gamma, const float* __restrict__ beta) {
    __shared__ float sb[256];
    int row = blockIdx.x, cch = row & (ECH - 1);
    const h2* xr = (const h2*)(X + (size_t)row * GN);
    h2* hr = (h2*)(H + (size_t)row * GN);
    float s = 0.f, ss = 0.f;
    for (int i = threadIdx.x; i < GN / 2; i += 256) {
        float2 v = __half22float2(xr[i]);
        s += v.x + v.y;
        ss += v.x * v.x + v.y * v.y;
    }
    float tot = brsum(s, sb), tot2 = brsum(ss, sb);
    const float inv = 1.0f / (float)GN;
    float mu = tot * inv, var = tot2 * inv - mu * mu;
    float rstd = rsqrtf(var + 1e-5f);
    float a = rstd * gamma[cch], bb = beta[cch] - mu * a;
    for (int i = threadIdx.x; i < GN / 2; i += 256) {
        float2 v = __half22float2(xr[i]);
        hr[i] = hi2(v.x * a + bb, v.y * a + bb);
    }
}

__global__ __launch_bounds__(256)
void softmax_hi(const float* __restrict__ P, __half* __restrict__ SH,
                int J, float scale, int nsplit) {
    __shared__ float rowbuf[512];
    __shared__ float sb[256];
    int row = blockIdx.x, b = row >> 8, i = row & 255, tid = threadIdx.x;
    for (int j = tid; j < J; j += 256) {
        float v = 0.f;
        for (int s = 0; s < nsplit; s++)
            v += P[(((size_t)(b * nsplit + s) * 256) + i) * J + j];
        rowbuf[j] = v * scale;
    }
    __syncthreads();
    float ls = 0.f;
    for (int j = tid; j < J; j += 256) ls += rowbuf[j];
    float mean = brsum(ls, sb) / (float)J;
    float lv = 0.f;
    for (int j = tid; j < J; j += 256) { float d = rowbuf[j] - mean; lv += d * d; }
    float rstd = rsqrtf(brsum(lv, sb) / (float)J + 1e-5f);
    float lm = -1e30f;
    for (int j = tid; j < J; j += 256) {
        float tt = (rowbuf[j] - mean) * rstd;
        rowbuf[j] = tt;
        lm = fmaxf(lm, tt);
    }
    float mx = brmax(lm, sb);
    float le = 0.f;
    for (int j = tid; j < J; j += 256) {
        float e = expf(rowbuf[j] - mx);
        rowbuf[j] = e;
        le += e;
    }
    float rden = 1.0f / brsum(le, sb);
    size_t ob = ((size_t)b * 256 + i) * J;
    for (int j = tid; j < J; j += 256)
        SH[ob + j] = __float2half_rn(rowbuf[j] * rden);
}

extern "C" void kernel_launch(void* const* d_in, const int* in_sizes, int n_in,
                              void* d_out, int out_size) {
    const float* feat = (const float*)d_in[0];
    const float* kv   = (const float*)d_in[1];
    const float* ag = (const float*)d_in[10];
    const float* ab = (const float*)d_in[11];
    const float* eg = (const float*)d_in[12];
    const float* eb = (const float*)d_in[13];
    float* out = (float*)d_out;

    float *pu, *plw;
    __half *emb, *pre, *fh, *nh, *qkvh, *th, *kvh, *suh, *slh, *wh;
    cudaGetSymbolAddress((void**)&emb, g_emb);
    cudaGetSymbolAddress((void**)&pre, g_pre);
    cudaGetSymbolAddress((void**)&pu, g_pu);
    cudaGetSymbolAddress((void**)&plw, g_plw);
    cudaGetSymbolAddress((void**)&fh, g_fh);
    cudaGetSymbolAddress((void**)&nh, g_nh);
    cudaGetSymbolAddress((void**)&qkvh, g_qkvh);
    cudaGetSymbolAddress((void**)&th, g_th);
    cudaGetSymbolAddress((void**)&kvh, g_kvh);
    cudaGetSymbolAddress((void**)&suh, g_suh);
    cudaGetSymbolAddress((void**)&slh, g_slh);
    cudaGetSymbolAddress((void**)&wh, g_wh);

    __half *qh = qkvh;
    __half *kh = qkvh + TOT4;
    __half *vh = qkvh + 2 * TOT4;

    cudaFuncSetAttribute(gemm_cp, cudaFuncAttributeMaxDynamicSharedMemorySize, CSMEM2);
    cudaFuncSetAttribute(gemmnt_cp, cudaFuncAttributeMaxDynamicSharedMemorySize, NSMEM);

    const float scale = 1.0f / 128.0f;
    dim3 blk(256);
    dim3 g8(GN / 64, 2, 8);
    dim3 g4(GN / 64, 2, 4);

    // #1 weights
    split_w8<<<dim3(64, 8), blk>>>((const float*)d_in[2], (const float*)d_in[3],
                                   (const float*)d_in[4], (const float*)d_in[5],
                                   (const float*)d_in[6], (const float*)d_in[7],
                                   (const float*)d_in[8], (const float*)d_in[9], wh);
    // #2 feat, #3 kv
    split_hi<<<32768, blk>>>(feat, fh, 8388608);
    split_hi<<<8192, blk>>>(kv, kvh, 2097152);
    // #4 emb = gelu(w_in @ feat) -> half
    gemm_cp<<<g8, blk, CSMEM2>>>(wh, 0, fh, BSTR, nullptr, emb,
                                 BSTR, 0, nullptr, 256, 1 | 32);
    // #5 nrm = inorm(emb)
    inorm_hh<<<NB * ECH, blk>>>(emb, nh, ag, ab);
    // #6 fused QKV (M=768) -> PROFILED
    gemm_cp<<<dim3(GN / 64, 6, 4), blk, CSMEM2>>>(wh + 2 * 65536, 0,
                                                  nh + TOT4, BSTR,
                                                  nullptr, qkvh, BSTR, TOT4,
                                                  nullptr, 256, 32);
    // #7 upper scores (nsplit=16)
    gemmnt_cp<<<dim3(2, 2, HB * 16), blk, NSMEM>>>(qh, BSTR, kh, BSTR, pu, 256, 16);
    // #8 softmax upper
    softmax_hi<<<HB * 256, blk>>>(pu, suh, 256, scale, 16);
    // #9 t = su @ v
    gemm_cp<<<g4, blk, CSMEM2>>>(suh, 65536, vh, BSTR, nullptr, th,
                                 BSTR, 0, nullptr, 256, 32);
    // #10 pre_u = wo_sa @ t + emb_u -> half
    gemm_cp<<<g4, blk, CSMEM2>>>(wh + 5 * 65536, 0, th, BSTR,
                                 nullptr, pre + TOT4, BSTR, 0,
                                 emb + TOT4, 256, 2 | 32);
    // #11 lower Ql
    gemm_cp<<<g4, blk, CSMEM2>>>(wh + 6 * 65536, 0, nh, BSTR,
                                 nullptr, qh, BSTR, 0, nullptr, 256, 32);
    // #12 lower scores (nsplit=8, kv shared)
    gemmnt_cp<<<dim3(4, 2, HB * 8), blk, NSMEM>>>(qh, BSTR, kvh, 0, plw, 512, 8);
    // #13 softmax lower
    softmax_hi<<<HB * 256, blk>>>(plw, slh, 512, scale, 8);
    // #14 ca = sl @ kv (K=512)
    gemm_cp<<<g4, blk, CSMEM2>>>(slh, 131072, kvh, 0, nullptr, th,
                                 BSTR, 0, nullptr, 512, 32);
    // #15 pre_l = wo_ca @ ca + emb_l -> half
    gemm_cp<<<g4, blk, CSMEM2>>>(wh + 7 * 65536, 0, th, BSTR,
                                 nullptr, pre, BSTR, 0, emb, 256, 2 | 32);
    // #16 nrm2 = inorm(pre)
    inorm_hh<<<NB * ECH, blk>>>(pre, nh, eg, eb);
    // #17 out = gelu(w_out @ nrm2) -> fp32
    gemm_cp<<<g8, blk, CSMEM2>>>(wh + 65536, 0, nh, BSTR, out, nullptr,
                                 BSTR, 0, nullptr, 256, 1 | 8);
}